// round 3
// baseline (speedup 1.0000x reference)
#include <cuda_runtime.h>

// filtfilt(butter(4,0.2)) over 512 independent rows of 48000 fp32 samples.
//
// Simplifications (exact to fp32 rounding / ~1e-6 rel):
//  1. scale divide/multiply cancels (whole pipeline is linear) -> skipped.
//  2. IIR poles: |p|max = 0.7955 -> 64-sample zero-state warm-up reproduces
//     the true filter state to ~4.5e-7 relative, so the serial recurrence
//     decouples into per-thread chunks (overlap-save). No scan needed.
//     Chunk 0 (fwd) and the last chunk (bwd) are EXACT (zero state matches
//     the reference's zero-padded init).
//
// One block per row; whole padded row lives in dynamic smem, skewed by one
// float so the 48000-sample body is 16B-aligned (vector LDS/STS). Global
// traffic = one float4 read of x + one float4 write of out (~196MB).

#define T_LEN   48000
#define PAD     15
#define TP      (T_LEN + 2 * PAD)   // 48030
#define SKEW    1                   // body starts at smem index SKEW+PAD = 16
#define NTH     256
#define CHUNK   189                 // odd -> conflict-free lane stride; 255*189 >= TP
#define WARM    64                  // 0.7955^64 ~ 4.5e-7

// FIR coefficients (b / a0), a0 = 1
#define B0f 0.004824343357716228f
#define B1f 0.019297373430864913f
#define B2f 0.02894606014629737f
// Negated IIR feedback: yn = f - a1*y1 - a2*y2 - a3*y3 - a4*y4
#define NA1 ( 2.369513007182038f)
#define NA2 (-2.3139884144006455f)
#define NA3 ( 1.0546654058785672f)
#define NA4 (-0.18737949236818502f)

// Reassociated so the loop-carried chain is only the final fma (4 cyc/sample):
// the first three fmas consume states >= 2 samples old.
__device__ __forceinline__ float iir_step(float f, float y1, float y2, float y3, float y4) {
    float c = fmaf(NA4, y4, f);
    c = fmaf(NA3, y3, c);
    c = fmaf(NA2, y2, c);
    return fmaf(NA1, y1, c);
}

__device__ __forceinline__ float fir5(float xc, float m1, float m2, float m3, float m4) {
    // b symmetric: b0*(x[t]+x[t-4]) + b1*(x[t-1]+x[t-3]) + b2*x[t-2]
    return fmaf(B0f, xc + m4, fmaf(B1f, m1 + m3, B2f * m2));
}

__global__ void __launch_bounds__(NTH, 1)
filtfilt_kernel(const float* __restrict__ x, float* __restrict__ out)
{
    extern __shared__ float smem_raw[];      // SKEW + TP floats
    float* __restrict__ s = smem_raw + SKEW; // padded row: s[0..TP)
    const int row = blockIdx.x;
    const float* __restrict__ xr = x + (long long)row * T_LEN;
    float* __restrict__ yr = out + (long long)row * T_LEN;
    const int tid = threadIdx.x;

    // ---- Phase 0: build odd-padded row in smem ----
    // Body: float4 gmem loads -> float4 smem stores (body at smem idx 16: aligned).
    {
        const float4* __restrict__ xr4 = (const float4*)xr;
        float4* __restrict__ sb4 = (float4*)(s + PAD);       // 16B-aligned
        for (int j4 = tid; j4 < T_LEN / 4; j4 += NTH)
            sb4[j4] = xr4[j4];
        // Edges: left[j] = 2x0 - x[14-j]; right[i] = 2x[T-1] - x[T-3-i]
        if (tid < 2 * PAD) {
            const float x0 = xr[0];
            const float xN = xr[T_LEN - 1];
            if (tid < PAD) {
                s[tid] = 2.0f * x0 - xr[PAD - 1 - tid];
            } else {
                int i = tid - PAD;
                s[T_LEN + PAD + i] = 2.0f * xN - xr[T_LEN - 3 - i];
            }
        }
    }
    __syncthreads();

    const int t0 = tid * CHUNK;
    const int t1 = min(t0 + CHUNK, TP);

    // ==================== FORWARD PASS ====================
    // Warm-up: read-only over the previous thread's (still pristine) region.
    float m1 = 0.f, m2 = 0.f, m3 = 0.f, m4 = 0.f;  // x[t-1..t-4]
    float y1 = 0.f, y2 = 0.f, y3 = 0.f, y4 = 0.f;  // y[t-1..t-4]
#pragma unroll 4
    for (int t = t0 - WARM; t < t0; ++t) {
        float xc = ((unsigned)t < (unsigned)TP) ? s[t] : 0.f;
        float f  = fir5(xc, m1, m2, m3, m4);
        float yn = iir_step(f, y1, y2, y3, y4);
        m4 = m3; m3 = m2; m2 = m1; m1 = xc;
        y4 = y3; y3 = y2; y2 = y1; y1 = yn;
    }
    __syncthreads();
    // Main: each thread touches only its own chunk; s[t] is read before it is
    // written (FIR history lives in registers) -> in-place is race-free.
#pragma unroll 4
    for (int t = t0; t < t1; ++t) {
        float xc = s[t];
        float f  = fir5(xc, m1, m2, m3, m4);
        float yn = iir_step(f, y1, y2, y3, y4);
        s[t] = yn;
        m4 = m3; m3 = m2; m2 = m1; m1 = xc;
        y4 = y3; y3 = y2; y2 = y1; y1 = yn;
    }
    __syncthreads();

    // ==================== BACKWARD PASS ====================
    // Same filter in reverse time over the forward output, in place.
    m1 = m2 = m3 = m4 = 0.f;
    y1 = y2 = y3 = y4 = 0.f;
#pragma unroll 4
    for (int t = t1 + WARM - 1; t >= t1; --t) {
        float xc = ((unsigned)t < (unsigned)TP) ? s[t] : 0.f;
        float f  = fir5(xc, m1, m2, m3, m4);
        float vn = iir_step(f, y1, y2, y3, y4);
        m4 = m3; m3 = m2; m2 = m1; m1 = xc;
        y4 = y3; y3 = y2; y2 = y1; y1 = vn;
    }
    __syncthreads();
#pragma unroll 4
    for (int t = t1 - 1; t >= t0; --t) {
        float xc = s[t];
        float f  = fir5(xc, m1, m2, m3, m4);
        float vn = iir_step(f, y1, y2, y3, y4);
        s[t] = vn;
        m4 = m3; m3 = m2; m2 = m1; m1 = xc;
        y4 = y3; y3 = y2; y2 = y1; y1 = vn;
    }
    __syncthreads();

    // ---- Output: out[t] = s[t + PAD]; vector LDS.128 + STG.128 ----
    {
        const float4* __restrict__ sb4 = (const float4*)(s + PAD);  // aligned
        float4* __restrict__ yr4 = (float4*)yr;
        for (int j4 = tid; j4 < T_LEN / 4; j4 += NTH)
            yr4[j4] = sb4[j4];
    }
}

extern "C" void kernel_launch(void* const* d_in, const int* in_sizes, int n_in,
                              void* d_out, int out_size)
{
    const float* x = (const float*)d_in[0];
    float* out = (float*)d_out;
    const int rows = in_sizes[0] / T_LEN;   // 8*64 = 512
    const int smem_bytes = (SKEW + TP) * (int)sizeof(float);

    cudaFuncSetAttribute(filtfilt_kernel,
                         cudaFuncAttributeMaxDynamicSharedMemorySize,
                         smem_bytes);
    filtfilt_kernel<<<rows, NTH, smem_bytes>>>(x, out);
}

// round 9
// speedup vs baseline: 1.5520x; 1.5520x over previous
#include <cuda_runtime.h>

// filtfilt(butter(4,0.2)) over 512 rows x 48000 fp32.
//
// Exact-to-~1e-5 simplifications:
//  1. scale divide/multiply cancels (pipeline is linear) -> skipped.
//  2. IIR poles |p|max=0.7955 -> 48-sample zero-state warm-up reproduces true
//     state to ~1.7e-5 (overlap-save), applied at TWO granularities:
//       - 4 blocks per row, each with a private 12096-float smem window
//       - ~49-sample thread chunks inside each block
//     Seg-0 forward / seg-3 backward are exact (zero warm-in from true
//     zero-state region).
//
// 47.25KB smem/block -> 4 blocks/SM (32 warps/SM) vs R3's 1 block/SM:
// fixes R3's latency-bound profile (occ 12.5%, issue 34%, DRAM 20.7%).

#define T_LEN   48000
#define PAD     15
#define TP      (T_LEN + 2 * PAD)     // 48030
#define NTH     256
#define NSEG    4
#define SEG_OUT 12000                 // output samples per block
#define WARM    48                    // 0.7955^48 ~ 1.7e-5
#define LEN     (SEG_OUT + 2 * WARM)  // window = 12096 floats = 47.25 KB
#define CHUNK_F 49                    // odd -> conflict-free; 246*49 >= LEN-WARM
#define CHUNK_B 47                    // odd; 256*47 >= SEG_OUT

// FIR b (a0=1), symmetric
#define B0f 0.004824343357716228f
#define B1f 0.019297373430864913f
#define B2f 0.02894606014629737f
// Negated IIR feedback: yn = f - a1*y1 - a2*y2 - a3*y3 - a4*y4
#define NA1 ( 2.369513007182038f)
#define NA2 (-2.3139884144006455f)
#define NA3 ( 1.0546654058785672f)
#define NA4 (-0.18737949236818502f)

// Loop-carried chain = final fma only (4 cyc/sample); earlier fmas use older state.
__device__ __forceinline__ float iir_step(float f, float y1, float y2, float y3, float y4) {
    float c = fmaf(NA4, y4, f);
    c = fmaf(NA3, y3, c);
    c = fmaf(NA2, y2, c);
    return fmaf(NA1, y1, c);
}
__device__ __forceinline__ float fir5(float xc, float m1, float m2, float m3, float m4) {
    return fmaf(B0f, xc + m4, fmaf(B1f, m1 + m3, B2f * m2));
}

__global__ void __launch_bounds__(NTH, 4)
filtfilt_kernel(const float* __restrict__ x, float* __restrict__ out)
{
    extern __shared__ float s[];            // LEN floats
    const int seg = blockIdx.x;             // 0..3
    const int row = blockIdx.y;
    const float* __restrict__ xr = x + (size_t)row * T_LEN;
    float* __restrict__ yr = out + (size_t)row * T_LEN;
    const int tid  = threadIdx.x;
    const int o0   = seg * SEG_OUT;         // first output sample of this block
    const int base = PAD + o0 - WARM;       // padded-domain index of s[0]

    // ---- Load window: s[i] = padded_x[base+i] (0 outside [0,TP)) ----
    // Bulk fast path covers g in [PAD, PAD+T_LEN). o0%4==0 and WARM%4==0 make
    // lo/hi 4-aligned and gmem/smem float4-aligned together.
    {
        const int lo = max(0, PAD - base);                  // 48 for seg 0, else 0
        const int hi = min(LEN, PAD + T_LEN - base);        // 12048 for seg 3, else LEN
        const float4* __restrict__ src4 = (const float4*)(xr + (base + lo - PAD));
        float4* __restrict__ dst4 = (float4*)(s + lo);
        const int n4 = (hi - lo) >> 2;
        for (int j4 = tid; j4 < n4; j4 += NTH)
            dst4[j4] = src4[j4];
        // Edge elements (seg 0 first 48 / seg 3 last 48): odd reflection pad.
        // left pad (g in [0,PAD)):        v = 2*x[0]   - x[PAD-1-g]
        // right pad (g in [PAD+T, TP)):   v = 2*x[T-1] - x[2T+PAD-3-g]
        for (int i = tid; i < LEN - (hi - lo); i += NTH) {
            int ii = (i < lo) ? i : (hi + i - lo);          // indices outside [lo,hi)
            int g = base + ii;
            float v = 0.f;
            if ((unsigned)g < (unsigned)TP) {
                if (g < PAD)               v = 2.f * xr[0] - xr[PAD - 1 - g];
                else if (g >= PAD + T_LEN) v = 2.f * xr[T_LEN - 1] - xr[2 * T_LEN + PAD - 3 - g];
                else                       v = xr[g - PAD];
            }
            s[ii] = v;
        }
    }
    __syncthreads();

    // ==================== FORWARD (in place) ====================
    // Targets [WARM, LEN): segment output region + right margin for bwd warm-up.
    {
        const int c0 = min(WARM + tid * CHUNK_F, LEN);
        const int c1 = min(c0 + CHUNK_F, LEN);
        float m1 = 0.f, m2 = 0.f, m3 = 0.f, m4 = 0.f;
        float y1 = 0.f, y2 = 0.f, y3 = 0.f, y4 = 0.f;
#pragma unroll 4
        for (int t = c0 - WARM; t < c0; ++t) {            // read-only, in [0,LEN)
            float xc = s[t];
            float f  = fir5(xc, m1, m2, m3, m4);
            float yn = iir_step(f, y1, y2, y3, y4);
            m4 = m3; m3 = m2; m2 = m1; m1 = xc;
            y4 = y3; y3 = y2; y2 = y1; y1 = yn;
        }
        __syncthreads();
#pragma unroll 4
        for (int t = c0; t < c1; ++t) {                   // own chunk: RAW-safe in place
            float xc = s[t];
            float f  = fir5(xc, m1, m2, m3, m4);
            float yn = iir_step(f, y1, y2, y3, y4);
            s[t] = yn;
            m4 = m3; m3 = m2; m2 = m1; m1 = xc;
            y4 = y3; y3 = y2; y2 = y1; y1 = yn;
        }
    }
    __syncthreads();

    // ==================== BACKWARD (in place) ====================
    // Targets [WARM, WARM+SEG_OUT); warm-up reads forward output in the right
    // margin; past the padded end (ilim) masked to 0 = reference zero state.
    {
        const int b0 = min(WARM + tid * CHUNK_B, WARM + SEG_OUT);
        const int b1 = min(b0 + CHUNK_B, WARM + SEG_OUT);
        const int ilim = TP - base;
        float m1 = 0.f, m2 = 0.f, m3 = 0.f, m4 = 0.f;
        float y1 = 0.f, y2 = 0.f, y3 = 0.f, y4 = 0.f;
#pragma unroll 4
        for (int t = b1 + WARM - 1; t >= b1; --t) {       // t < b1+WARM <= LEN
            float xc = (t < ilim) ? s[t] : 0.f;
            float f  = fir5(xc, m1, m2, m3, m4);
            float vn = iir_step(f, y1, y2, y3, y4);
            m4 = m3; m3 = m2; m2 = m1; m1 = xc;
            y4 = y3; y3 = y2; y2 = y1; y1 = vn;
        }
        __syncthreads();
#pragma unroll 4
        for (int t = b1 - 1; t >= b0; --t) {
            float xc = s[t];
            float f  = fir5(xc, m1, m2, m3, m4);
            float vn = iir_step(f, y1, y2, y3, y4);
            s[t] = vn;
            m4 = m3; m3 = m2; m2 = m1; m1 = xc;
            y4 = y3; y3 = y2; y2 = y1; y1 = vn;
        }
    }
    __syncthreads();

    // ---- Output: out[o0+j] = s[WARM+j]; both sides 16B-aligned ----
    {
        const float4* __restrict__ sb4 = (const float4*)(s + WARM);
        float4* __restrict__ yr4 = (float4*)(yr + o0);
        for (int j4 = tid; j4 < SEG_OUT / 4; j4 += NTH)
            yr4[j4] = sb4[j4];
    }
}

extern "C" void kernel_launch(void* const* d_in, const int* in_sizes, int n_in,
                              void* d_out, int out_size)
{
    const float* x = (const float*)d_in[0];
    float* out = (float*)d_out;
    const int rows = in_sizes[0] / T_LEN;            // 512
    const int smem_bytes = LEN * (int)sizeof(float); // 48384

    cudaFuncSetAttribute(filtfilt_kernel,
                         cudaFuncAttributeMaxDynamicSharedMemorySize,
                         smem_bytes);
    dim3 grid(NSEG, rows);
    filtfilt_kernel<<<grid, NTH, smem_bytes>>>(x, out);
}